// round 2
// baseline (speedup 1.0000x reference)
#include <cuda_runtime.h>

#define NN 768
#define NF 128
#define MF 256
#define GF 256
#define ALPHA 0.01f
#define INV_CNT (1.0f / (NN * NF))

// ---------------- scratch (no allocations allowed) ----------------
__device__ __align__(16) float g_msg[NN * MF];    // nodes @ we
__device__ __align__(16) float g_ebar[NN * MF];   // sum_j leaky(b + msg*e)
__device__ __align__(16) float g_pre[NN * NF];    // pre-layernorm new_nodes
__device__ float g_stats[2];                      // sum, sumsq
__device__ float g_colsum[NF];                    // column sums of g_pre

__device__ __forceinline__ float leaky(float x) { return fmaxf(x, ALPHA * x); }

// ---------------- K1: msg = nodes @ we  (768x128 @ 128x256) ----------------
// 96 blocks x 256 threads; block = 8 rows x 256 cols. Also zeroes reducers.
__global__ void k1_msg(const float* __restrict__ nodes, const float* __restrict__ we) {
    __shared__ float ns[8][NF];
    const int tx = threadIdx.x;
    const int i0 = blockIdx.x * 8;

    if (blockIdx.x == 0) {
        if (tx < 2) g_stats[tx] = 0.0f;
        if (tx < NF) g_colsum[tx] = 0.0f;
    }

    for (int t = tx; t < 8 * NF; t += 256) {
        ns[t >> 7][t & 127] = nodes[i0 * NF + t];
    }
    __syncthreads();

    float acc[8];
#pragma unroll
    for (int r = 0; r < 8; r++) acc[r] = 0.0f;

    for (int c = 0; c < NF; c++) {
        const float w = we[c * MF + tx];
#pragma unroll
        for (int r = 0; r < 8; r++) acc[r] = fmaf(ns[r][c], w, acc[r]);
    }
#pragma unroll
    for (int r = 0; r < 8; r++) g_msg[(i0 + r) * MF + tx] = acc[r];
}

// ---------------- K2: ebar[i,k] = sum_j leaky(b[k] + msg[j,k]*edges[i,j]) --
// grid (192, 2), 128 threads. Block = 4 rows (i) x 128 cols (k-half).
// 384 blocks -> ~2.6 waves on 148 SMs (better balance than 192 blocks).
#define TI 4
#define TJ 128
__global__ void __launch_bounds__(128) k2_ebar(const float* __restrict__ edges,
                                               const float* __restrict__ b) {
    __shared__ float es[TI][TJ];
    const int tx = threadIdx.x;
    const int k  = blockIdx.y * 128 + tx;
    const int i0 = blockIdx.x * TI;
    const float bk = b[k];

    float acc[TI];
#pragma unroll
    for (int r = 0; r < TI; r++) acc[r] = 0.0f;

    for (int jt = 0; jt < NN; jt += TJ) {
#pragma unroll
        for (int r = 0; r < TI; r++)
            es[r][tx] = edges[(i0 + r) * NN + jt + tx];
        __syncthreads();

#pragma unroll 8
        for (int j = 0; j < TJ; j++) {
            const float m = __ldg(&g_msg[(jt + j) * MF + k]);
#pragma unroll
            for (int r = 0; r < TI; r++) {
                const float t = fmaf(m, es[r][j], bk);
                acc[r] += fmaxf(t, ALPHA * t);
            }
        }
        __syncthreads();
    }
#pragma unroll
    for (int r = 0; r < TI; r++) g_ebar[(i0 + r) * MF + k] = acc[r];
}

// ---------------- K3: pre = leaky(ebar @ wv) + nodes; partial stats --------
// 192 blocks x 128 threads; block = 4 rows x 128 cols.
__global__ void k3_pre(const float* __restrict__ nodes, const float* __restrict__ wv) {
    __shared__ float eb[4][MF];
    __shared__ float red[128];
    const int tx = threadIdx.x;
    const int i0 = blockIdx.x * 4;

    for (int t = tx; t < 4 * MF; t += 128) {
        eb[t >> 8][t & 255] = g_ebar[i0 * MF + t];
    }
    __syncthreads();

    float acc[4];
#pragma unroll
    for (int r = 0; r < 4; r++) acc[r] = 0.0f;

    for (int c = 0; c < MF; c++) {
        const float w = wv[c * NF + tx];
#pragma unroll
        for (int r = 0; r < 4; r++) acc[r] = fmaf(eb[r][c], w, acc[r]);
    }

    float lsum = 0.0f, lss = 0.0f;
#pragma unroll
    for (int r = 0; r < 4; r++) {
        const float v = leaky(acc[r]) + nodes[(i0 + r) * NF + tx];
        g_pre[(i0 + r) * NF + tx] = v;
        lsum += v;
        lss = fmaf(v, v, lss);
    }
    atomicAdd(&g_colsum[tx], lsum);   // thread tx owns column tx

    // block-reduce sum and sumsq
    red[tx] = lsum;
    __syncthreads();
    for (int s = 64; s > 0; s >>= 1) {
        if (tx < s) red[tx] += red[tx + s];
        __syncthreads();
    }
    if (tx == 0) atomicAdd(&g_stats[0], red[0]);
    __syncthreads();
    red[tx] = lss;
    __syncthreads();
    for (int s = 64; s > 0; s >>= 1) {
        if (tx < s) red[tx] += red[tx + s];
        __syncthreads();
    }
    if (tx == 0) atomicAdd(&g_stats[1], red[0]);
}

// ---------------- K4: new_features = leaky(gsum_norm @ wu) + features ------
// 1 block x 256 threads.
__global__ void k4_feat(const float* __restrict__ features, const float* __restrict__ wu,
                        float* __restrict__ out_feat) {
    __shared__ float gs[NF];
    const int tx = threadIdx.x;
    const float s = g_stats[0], ss = g_stats[1];
    const float mu = s * INV_CNT;
    const float var = ss * INV_CNT - mu * mu;
    const float rs = rsqrtf(var + 1e-5f);
    if (tx < NF) gs[tx] = (g_colsum[tx] - (float)NN * mu) * rs;
    __syncthreads();

    float acc = 0.0f;
    for (int c = 0; c < NF; c++) acc = fmaf(gs[c], wu[c * GF + tx], acc);
    out_feat[tx] = leaky(acc) + features[tx];
}

// ---------------- K5: normalize new_nodes into d_out ----------------------
// 96 blocks x 256 threads, float4.
__global__ void k5_norm(float4* __restrict__ out) {
    const int idx = blockIdx.x * blockDim.x + threadIdx.x;
    const float s = g_stats[0], ss = g_stats[1];
    const float mu = s * INV_CNT;
    const float var = ss * INV_CNT - mu * mu;
    const float rs = rsqrtf(var + 1e-5f);
    const float4 v = reinterpret_cast<const float4*>(g_pre)[idx];
    float4 o;
    o.x = (v.x - mu) * rs;
    o.y = (v.y - mu) * rs;
    o.z = (v.z - mu) * rs;
    o.w = (v.w - mu) * rs;
    out[idx] = o;
}

// ---------------- launch ---------------------------------------------------
extern "C" void kernel_launch(void* const* d_in, const int* in_sizes, int n_in,
                              void* d_out, int out_size) {
    (void)in_sizes; (void)n_in; (void)out_size;
    const float* nodes    = (const float*)d_in[0];
    const float* edges    = (const float*)d_in[1];
    const float* features = (const float*)d_in[2];
    const float* we       = (const float*)d_in[3];
    const float* b        = (const float*)d_in[4];
    const float* wv       = (const float*)d_in[5];
    const float* wu       = (const float*)d_in[6];

    float* out       = (float*)d_out;
    float* out_nodes = out;                       // [768*128]
    float* out_edges = out + NN * NF;             // [768*768]
    float* out_feat  = out + NN * NF + NN * NN;   // [256]

    cudaMemcpyAsync(out_edges, edges, (size_t)NN * NN * sizeof(float),
                    cudaMemcpyDeviceToDevice);

    k1_msg<<<96, 256>>>(nodes, we);
    dim3 g2(192, 2);
    k2_ebar<<<g2, 128>>>(edges, b);
    k3_pre<<<192, 128>>>(nodes, wv);
    k4_feat<<<1, 256>>>(features, wu, out_feat);
    k5_norm<<<96, 256>>>((float4*)out_nodes);
}